// round 15
// baseline (speedup 1.0000x reference)
#include <cuda_runtime.h>
#include <cstdint>

// C = triu(A @ B), A,B upper-triangular fp32, N=4096, sm_103 base target.
// bf16 mma.sync.m16n8k16, 3-term split:
//   hi = bf16(x), lo = bf16(x - hi);  C = Ahi*Bhi + Ahi*Blo + Alo*Bhi
//
// R13: two independent CTAs per SM. 256-thread CTA, 8 warps of 32x32,
// tile 128x64 (~105 regs -> __launch_bounds__(256,2) safe; smem 59.4KB x2 =
// 118.7KB). Two CTAs' barriers are independent: one CTA's mma covers the
// other's post-barrier LDS burst (R12's 47% idle was single-CTA lockstep).
// bf16 hi/lo pre-split at staging; inner loop pure LDS+mma. Conflict-free
// pitches: A:20 (banks 20g+tq), B:72 (banks 8tq+g). Tiles ordered longest
// k-span first; strictly-lower 128x64 blocks zero-filled by tail CTAs.

#define NN 4096
#define BK 32
#define THREADS 256
#define N_WORK 1056
#define N_ZERO 992

// u32 units. A: [row][pair] 128x16 (+4 pad); B: [pair][n] 16x64 (+8 pad).
#define AP 20
#define BP 72
#define A_U (128 * AP)               // 2560
#define B_U (16 * BP)                // 1152
#define OAH 0
#define OAL A_U
#define OBH (2 * A_U)
#define OBL (2 * A_U + B_U)
#define BUF_U (2 * A_U + 2 * B_U)    // 7424
#define SMEM_BYTES (2 * BUF_U * 4)   // 59392 (x2 CTAs = 118.8KB)

static __device__ __forceinline__ uint32_t pack_bf16x2(float f0, float f1) {
    uint32_t r;
    asm("cvt.rn.bf16x2.f32 %0, %1, %2;" : "=r"(r) : "f"(f1), "f"(f0));
    return r;
}
static __device__ __forceinline__ void split2(float f0, float f1,
                                              uint32_t& h, uint32_t& l) {
    h = pack_bf16x2(f0, f1);
    float h0 = __uint_as_float(h << 16);
    float h1 = __uint_as_float(h & 0xFFFF0000u);
    l = pack_bf16x2(f0 - h0, f1 - h1);
}
static __device__ __forceinline__ void mma16(float* d, const uint32_t* a,
                                             const uint32_t* b) {
    asm volatile(
        "mma.sync.aligned.m16n8k16.row.col.f32.bf16.bf16.f32 "
        "{%0,%1,%2,%3}, {%4,%5,%6,%7}, {%8,%9}, {%0,%1,%2,%3};"
        : "+f"(d[0]), "+f"(d[1]), "+f"(d[2]), "+f"(d[3])
        : "r"(a[0]), "r"(a[1]), "r"(a[2]), "r"(a[3]), "r"(b[0]), "r"(b[1]));
}

__global__ __launch_bounds__(THREADS, 2)
void triu_mm_bf16(const float* __restrict__ A, const float* __restrict__ B,
                  float* __restrict__ C) {
    const int t = blockIdx.x;
    const int tid = threadIdx.x;

    if (t >= N_WORK) {
        // Strictly-lower 128x64 block: exactly zero.
        int rem = t - N_WORK, bi = 0, bj64 = 0;
        #pragma unroll 1
        for (int b = 1; b < 32; ++b) {
            if (rem < 2 * b) { bi = b; bj64 = rem; break; }
            rem -= 2 * b;
        }
        const float4 z = make_float4(0.f, 0.f, 0.f, 0.f);
        const int rowBase = bi * 128, colBase = bj64 * 64;
        #pragma unroll
        for (int it = 0; it < 8; ++it) {
            int idx = it * 256 + tid;        // 2048 float4 in 128x64 tile
            int r = idx >> 4, c4 = idx & 15;
            *reinterpret_cast<float4*>(
                C + (size_t)(rowBase + r) * NN + colBase + c4 * 4) = z;
        }
        return;
    }

    // Work tile t -> (bi, bj64); longest k-span (largest dd) first.
    int bi = 0, bj64 = 0;
    {
        int rem = t;
        #pragma unroll 1
        for (int dd = 63; dd >= 0; --dd) {
            int cnt = (63 - dd) / 2 + 1;
            if (rem < cnt) { bi = rem; bj64 = 2 * rem + dd; break; }
            rem -= cnt;
        }
    }
    const int rowBase = bi * 128, colBase = bj64 * 64;
    const int kStart = rowBase, kEnd = (bj64 + 1) * 64;
    const int nSteps = (kEnd - kStart) / BK;   // >= 2

    extern __shared__ uint32_t smem[];

    const int lane = tid & 31, wid = tid >> 5;
    const int wm = (wid & 3) * 32;        // 4 warps down (128)
    const int wn = (wid >> 2) * 32;       // 2 warps across (64)
    const int g = lane >> 2, tq = lane & 3;

    // Staging maps.
    // A: 128 rows x 8 float4; 2 threads/row, 4 float4 (=8 pairs) each.
    const int ar = tid >> 1, aq = tid & 1;
    // B: 16 pair-rows x 16 n-float4; thread = (pair-row, n-quad), 2 float4.
    const int bp = tid >> 4, bc = tid & 15;

    float acc[2][4][4];
    #pragma unroll
    for (int mt = 0; mt < 2; ++mt)
        #pragma unroll
        for (int nt = 0; nt < 4; ++nt)
            #pragma unroll
            for (int i = 0; i < 4; ++i) acc[mt][nt][i] = 0.f;

    float4 pa0, pa1, pa2, pa3, pb0, pb1;
    {
        const float* ab = A + (size_t)(rowBase + ar) * NN + kStart + aq * 16;
        pa0 = *reinterpret_cast<const float4*>(ab);
        pa1 = *reinterpret_cast<const float4*>(ab + 4);
        pa2 = *reinterpret_cast<const float4*>(ab + 8);
        pa3 = *reinterpret_cast<const float4*>(ab + 12);
        const float* bb = B + (size_t)(kStart + 2 * bp) * NN + colBase + bc * 4;
        pb0 = *reinterpret_cast<const float4*>(bb);
        pb1 = *reinterpret_cast<const float4*>(bb + NN);
    }

    int curBuf = 0;

    // Stage tile 0 (split to bf16 hi/lo).
    {
        uint32_t* buf = smem;
        uint32_t h[4], l[4];
        split2(pa0.x, pa0.y, h[0], l[0]);
        split2(pa0.z, pa0.w, h[1], l[1]);
        split2(pa1.x, pa1.y, h[2], l[2]);
        split2(pa1.z, pa1.w, h[3], l[3]);
        *reinterpret_cast<uint4*>(buf + OAH + ar * AP + aq * 8) =
            make_uint4(h[0], h[1], h[2], h[3]);
        *reinterpret_cast<uint4*>(buf + OAL + ar * AP + aq * 8) =
            make_uint4(l[0], l[1], l[2], l[3]);
        split2(pa2.x, pa2.y, h[0], l[0]);
        split2(pa2.z, pa2.w, h[1], l[1]);
        split2(pa3.x, pa3.y, h[2], l[2]);
        split2(pa3.z, pa3.w, h[3], l[3]);
        *reinterpret_cast<uint4*>(buf + OAH + ar * AP + aq * 8 + 4) =
            make_uint4(h[0], h[1], h[2], h[3]);
        *reinterpret_cast<uint4*>(buf + OAL + ar * AP + aq * 8 + 4) =
            make_uint4(l[0], l[1], l[2], l[3]);
        split2(pb0.x, pb1.x, h[0], l[0]);
        split2(pb0.y, pb1.y, h[1], l[1]);
        split2(pb0.z, pb1.z, h[2], l[2]);
        split2(pb0.w, pb1.w, h[3], l[3]);
        *reinterpret_cast<uint4*>(buf + OBH + bp * BP + bc * 4) =
            make_uint4(h[0], h[1], h[2], h[3]);
        *reinterpret_cast<uint4*>(buf + OBL + bp * BP + bc * 4) =
            make_uint4(l[0], l[1], l[2], l[3]);
    }
    __syncthreads();

    #pragma unroll 1
    for (int step = 0; step < nSteps; ++step) {
        const bool hasNext = (step + 1) < nSteps;

        if (hasNext) {
            const int kN = kStart + (step + 1) * BK;
            const float* ab = A + (size_t)(rowBase + ar) * NN + kN + aq * 16;
            pa0 = *reinterpret_cast<const float4*>(ab);
            pa1 = *reinterpret_cast<const float4*>(ab + 4);
            pa2 = *reinterpret_cast<const float4*>(ab + 8);
            pa3 = *reinterpret_cast<const float4*>(ab + 12);
            const float* bb = B + (size_t)(kN + 2 * bp) * NN + colBase + bc * 4;
            pb0 = *reinterpret_cast<const float4*>(bb);
            pb1 = *reinterpret_cast<const float4*>(bb + NN);
        }

        const uint32_t* buf = smem + curBuf * BUF_U;
        #pragma unroll
        for (int s = 0; s < 2; ++s) {
            const int ps = s * 8;

            uint32_t ah[2][4], al[2][4], bh[4][2], bl[4][2];
            #pragma unroll
            for (int mt = 0; mt < 2; ++mt) {
                const int r0 = wm + mt * 16 + g;
                ah[mt][0] = buf[OAH + r0 * AP + ps + tq];
                ah[mt][1] = buf[OAH + (r0 + 8) * AP + ps + tq];
                ah[mt][2] = buf[OAH + r0 * AP + ps + tq + 4];
                ah[mt][3] = buf[OAH + (r0 + 8) * AP + ps + tq + 4];
                al[mt][0] = buf[OAL + r0 * AP + ps + tq];
                al[mt][1] = buf[OAL + (r0 + 8) * AP + ps + tq];
                al[mt][2] = buf[OAL + r0 * AP + ps + tq + 4];
                al[mt][3] = buf[OAL + (r0 + 8) * AP + ps + tq + 4];
            }
            #pragma unroll
            for (int nt = 0; nt < 4; ++nt) {
                const int c0 = wn + nt * 8 + g;
                bh[nt][0] = buf[OBH + (ps + tq) * BP + c0];
                bh[nt][1] = buf[OBH + (ps + tq + 4) * BP + c0];
                bl[nt][0] = buf[OBL + (ps + tq) * BP + c0];
                bl[nt][1] = buf[OBL + (ps + tq + 4) * BP + c0];
            }

            #pragma unroll
            for (int mt = 0; mt < 2; ++mt)
                #pragma unroll
                for (int nt = 0; nt < 4; ++nt)
                    mma16(acc[mt][nt], ah[mt], bh[nt]);
            #pragma unroll
            for (int mt = 0; mt < 2; ++mt)
                #pragma unroll
                for (int nt = 0; nt < 4; ++nt)
                    mma16(acc[mt][nt], ah[mt], bl[nt]);
            #pragma unroll
            for (int mt = 0; mt < 2; ++mt)
                #pragma unroll
                for (int nt = 0; nt < 4; ++nt)
                    mma16(acc[mt][nt], al[mt], bh[nt]);
        }

        if (hasNext) {
            uint32_t* nb = smem + (curBuf ^ 1) * BUF_U;
            uint32_t h[4], l[4];
            split2(pa0.x, pa0.y, h[0], l[0]);
            split2(pa0.z, pa0.w, h[1], l[1]);
            split2(pa1.x, pa1.y, h[2], l[2]);
            split2(pa1.z, pa1.w, h[3], l[3]);
            *reinterpret_cast<uint4*>(nb + OAH + ar * AP + aq * 8) =
                make_uint4(h[0], h[1], h[2], h[3]);
            *reinterpret_cast<uint4*>(nb + OAL + ar * AP + aq * 8) =
                make_uint4(l[0], l[1], l[2], l[3]);
            split2(pa2.x, pa2.y, h[0], l[0]);
            split2(pa2.z, pa2.w, h[1], l[1]);
            split2(pa3.x, pa3.y, h[2], l[2]);
            split2(pa3.z, pa3.w, h[3], l[3]);
            *reinterpret_cast<uint4*>(nb + OAH + ar * AP + aq * 8 + 4) =
                make_uint4(h[0], h[1], h[2], h[3]);
            *reinterpret_cast<uint4*>(nb + OAL + ar * AP + aq * 8 + 4) =
                make_uint4(l[0], l[1], l[2], l[3]);
            split2(pb0.x, pb1.x, h[0], l[0]);
            split2(pb0.y, pb1.y, h[1], l[1]);
            split2(pb0.z, pb1.z, h[2], l[2]);
            split2(pb0.w, pb1.w, h[3], l[3]);
            *reinterpret_cast<uint4*>(nb + OBH + bp * BP + bc * 4) =
                make_uint4(h[0], h[1], h[2], h[3]);
            *reinterpret_cast<uint4*>(nb + OBL + bp * BP + bc * 4) =
                make_uint4(l[0], l[1], l[2], l[3]);
            curBuf ^= 1;
        }
        __syncthreads();
    }

    // Epilogue: fragment layout direct to global (float2, sector-coalesced).
    #pragma unroll
    for (int mt = 0; mt < 2; ++mt) {
        #pragma unroll
        for (int nt = 0; nt < 4; ++nt) {
            const int r0 = rowBase + wm + mt * 16 + g;
            const int c0 = colBase + wn + nt * 8 + tq * 2;
            float2 v01 = make_float2(acc[mt][nt][0], acc[mt][nt][1]);
            float2 v23 = make_float2(acc[mt][nt][2], acc[mt][nt][3]);
            *reinterpret_cast<float2*>(C + (size_t)r0 * NN + c0) = v01;
            *reinterpret_cast<float2*>(C + (size_t)(r0 + 8) * NN + c0) = v23;
        }
    }
}

extern "C" void kernel_launch(void* const* d_in, const int* in_sizes, int n_in,
                              void* d_out, int out_size) {
    const float* A = (const float*)d_in[0];
    const float* B = (const float*)d_in[1];
    float* C = (float*)d_out;

    cudaFuncSetAttribute(triu_mm_bf16,
                         cudaFuncAttributeMaxDynamicSharedMemorySize, SMEM_BYTES);
    triu_mm_bf16<<<N_WORK + N_ZERO, THREADS, SMEM_BYTES>>>(A, B, C);
}